// round 7
// baseline (speedup 1.0000x reference)
#include <cuda_runtime.h>
#include <cuda_bf16.h>
#include <math_constants.h>

// ShiftNMF: out[n,m] = Re( sum_d softplus(W[n,d]) * exp(-2*pi*i*tau[n,d]*m/M) * Hft[d,m] )
// Hft = full FFT of softplus(H) (reference's rfft+mirror == full FFT of real signal).
// Output dtype float32 (harness coerces complex ref to real part), out_size = N*M.

#define N_ROWS 1024
#define RANK   16
#define M_LEN  4096
#define LOG2M  12

__device__ float2 g_Hft[RANK * M_LEN];   // device-global scratch (no allocation)

__device__ __forceinline__ float softplus_accurate(float x) {
    return (x > 20.0f) ? x : log1pf(expf(x));
}

// ---------------------------------------------------------------------------
// Kernel 1: 16 x 4096-pt FFT of softplus(H) rows. One CTA per row, 1024 thr.
// (unchanged from passing round)
// ---------------------------------------------------------------------------
#define FFT_THREADS 1024

__global__ void __launch_bounds__(FFT_THREADS) fft_hft_kernel(const float* __restrict__ H) {
    __shared__ float2 buf[M_LEN];        // 32 KB
    __shared__ float2 tw[M_LEN / 2];     // 16 KB twiddle table
    const int row = blockIdx.x;
    const int tid = threadIdx.x;

    for (int j = tid; j < M_LEN / 2; j += FFT_THREADS) {
        float s, c;
        sincospif(-2.0f * (float)j / (float)M_LEN, &s, &c);
        tw[j] = make_float2(c, s);
    }
    for (int i = tid; i < M_LEN; i += FFT_THREADS) {
        int j = __brev((unsigned)i) >> (32 - LOG2M);
        float v = softplus_accurate(H[row * M_LEN + i]);
        buf[j] = make_float2(v, 0.0f);
    }
    __syncthreads();

    #pragma unroll 1
    for (int s = 1; s <= LOG2M; s++) {
        const int half = 1 << (s - 1);
        const int tsh  = LOG2M - s;
        for (int j = tid; j < (M_LEN / 2); j += FFT_THREADS) {
            int k   = j & (half - 1);
            int grp = j >> (s - 1);
            int i1  = grp * (half << 1) + k;
            int i2  = i1 + half;
            float2 w = tw[k << tsh];
            float2 a = buf[i1];
            float2 b = buf[i2];
            float tr = w.x * b.x - w.y * b.y;
            float ti = w.x * b.y + w.y * b.x;
            buf[i2] = make_float2(a.x - tr, a.y - ti);
            buf[i1] = make_float2(a.x + tr, a.y + ti);
        }
        __syncthreads();
    }

    for (int i = tid; i < M_LEN; i += FFT_THREADS) {
        g_Hft[row * M_LEN + i] = buf[i];
    }
}

// ---------------------------------------------------------------------------
// Kernel 2: warp owns TWO n rows (halves LDS bytes per FFMA); lanes span m.
// CTA = 256 threads = 8 warps -> 16 n rows; m-chunk = 256.
// 4 d-passes of 4 ranks. Chebyshev recurrence with in-place role-alternating
// double buffer: B = fma(k, A, -B) / A = fma(k, B, -A)  (neg folds into FFMA,
// zero MOVs). acc[2][8] persists across passes.
// ---------------------------------------------------------------------------
#define CHUNK_M 256
#define DPASS   4
#define NPASSES (RANK / DPASS)
#define ROWS_W  2
#define WARPS_PER_CTA 8

__global__ void __launch_bounds__(256, 3) shiftnmf_main_kernel(
    const float* __restrict__ W,
    const float* __restrict__ tau,
    float* __restrict__ out,
    unsigned long long max_elems)
{
    __shared__ float2 sh[DPASS * CHUNK_M];   // 8 KB

    const int tid    = threadIdx.x;
    const int lane   = tid & 31;
    const int warp   = tid >> 5;
    const int m_base = blockIdx.x * CHUNK_M;
    const int n0     = (blockIdx.y * WARPS_PER_CTA + warp) * ROWS_W;

    float acc[ROWS_W][8];
    #pragma unroll
    for (int r = 0; r < ROWS_W; r++)
        #pragma unroll
        for (int i = 0; i < 8; i++) acc[r][i] = 0.0f;

    const float inv_m = 1.0f / (float)M_LEN;
    const int m0 = m_base + lane;

    #pragma unroll 1
    for (int pass = 0; pass < NPASSES; pass++) {
        const int dbase = pass * DPASS;

        // Rotator state: A = x at current m0, B = x at m0-32 (one step back).
        float xa[ROWS_W][DPASS], xb[ROWS_W][DPASS];
        float ya[ROWS_W][DPASS], yb[ROWS_W][DPASS];
        float kk[ROWS_W][DPASS];
        #pragma unroll
        for (int r = 0; r < ROWS_W; r++) {
            #pragma unroll
            for (int d = 0; d < DPASS; d++) {
                float t  = __ldg(&tau[(n0 + r) * RANK + dbase + d]);
                float sw = softplus_accurate(__ldg(&W[(n0 + r) * RANK + dbase + d]));
                float s0, c0;
                sincospif(-2.0f * t * ((float)m0 * inv_m), &s0, &c0);
                float cr = sw * c0;
                float ci = sw * s0;
                float ss, cs;
                sincospif(-2.0f * t * (32.0f * inv_m), &ss, &cs);  // om = (cs, ss)
                kk[r][d] = 2.0f * cs;
                xa[r][d] = cr;
                ya[r][d] = ci;
                // x_{-1} = x_0 * conj(om)
                xb[r][d] = fmaf(cr, cs,  ci * ss);
                yb[r][d] = fmaf(ci, cs, -cr * ss);
            }
        }

        __syncthreads();   // previous pass's smem reads done
        // Load this pass's 4 rows x 256 complex (512 float4, 2 per thread).
        #pragma unroll
        for (int q = 0; q < 2; q++) {
            int idx = q * 256 + tid;
            int d   = idx >> 7;               // / 128 float4 per row
            int e   = idx & 127;
            float4 v = *reinterpret_cast<const float4*>(
                &g_Hft[(dbase + d) * M_LEN + m_base + e * 2]);
            *reinterpret_cast<float4*>(&sh[d * CHUNK_M + e * 2]) = v;
        }
        __syncthreads();

        // 8 m-iterations, unrolled in pairs with role alternation (MOV-free).
        #pragma unroll
        for (int ip = 0; ip < 4; ip++) {
            // even iteration: cur = A, prev = B; B <- next
            {
                const int it = ip * 2;
                const int ml = it * 32 + lane;
                #pragma unroll
                for (int d = 0; d < DPASS; d++) {
                    float2 h = sh[d * CHUNK_M + ml];
                    #pragma unroll
                    for (int r = 0; r < ROWS_W; r++) {
                        float a = acc[r][it];
                        a = fmaf(xa[r][d], h.x, a);
                        a = fmaf(-ya[r][d], h.y, a);
                        acc[r][it] = a;
                        xb[r][d] = fmaf(kk[r][d], xa[r][d], -xb[r][d]);
                        yb[r][d] = fmaf(kk[r][d], ya[r][d], -yb[r][d]);
                    }
                }
            }
            // odd iteration: cur = B, prev = A; A <- next
            {
                const int it = ip * 2 + 1;
                const int ml = it * 32 + lane;
                #pragma unroll
                for (int d = 0; d < DPASS; d++) {
                    float2 h = sh[d * CHUNK_M + ml];
                    #pragma unroll
                    for (int r = 0; r < ROWS_W; r++) {
                        float a = acc[r][it];
                        a = fmaf(xb[r][d], h.x, a);
                        a = fmaf(-yb[r][d], h.y, a);
                        acc[r][it] = a;
                        xa[r][d] = fmaf(kk[r][d], xb[r][d], -xa[r][d]);
                        ya[r][d] = fmaf(kk[r][d], yb[r][d], -ya[r][d]);
                    }
                }
            }
        }
    }

    #pragma unroll
    for (int r = 0; r < ROWS_W; r++) {
        const unsigned long long row_base =
            (unsigned long long)(n0 + r) * M_LEN + m_base;
        #pragma unroll
        for (int i = 0; i < 8; i++) {
            unsigned long long fi = row_base + (unsigned long long)(i * 32 + lane);
            if (fi < max_elems) out[fi] = acc[r][i];
        }
    }
}

// ---------------------------------------------------------------------------
extern "C" void kernel_launch(void* const* d_in, const int* in_sizes, int n_in,
                              void* d_out, int out_size) {
    // H = strictly largest input; remaining two in given order = W, tau_tilde.
    int hi = 0;
    for (int i = 1; i < n_in; i++)
        if (in_sizes[i] > in_sizes[hi]) hi = i;

    const float* H = (const float*)d_in[hi];
    const float* wt[2] = {nullptr, nullptr};
    int nwt = 0;
    for (int i = 0; i < n_in && nwt < 2; i++)
        if (i != hi) wt[nwt++] = (const float*)d_in[i];
    const float* W   = wt[0];
    const float* tau = (wt[1] != nullptr) ? wt[1] : wt[0];

    float* out = (float*)d_out;

    unsigned long long max_elems = (unsigned long long)out_size;
    const unsigned long long full = (unsigned long long)N_ROWS * M_LEN;
    if (max_elems > full) max_elems = full;

    fft_hft_kernel<<<RANK, FFT_THREADS>>>(H);

    dim3 grid(M_LEN / CHUNK_M, N_ROWS / (WARPS_PER_CTA * ROWS_W));  // (16, 64)
    shiftnmf_main_kernel<<<grid, 256>>>(W, tau, out, max_elems);
}

// round 8
// speedup vs baseline: 1.1536x; 1.1536x over previous
#include <cuda_runtime.h>
#include <cuda_bf16.h>
#include <math_constants.h>

// ShiftNMF: out[n,m] = Re( sum_d softplus(W[n,d]) * exp(-2*pi*i*tau[n,d]*m/M) * Hft[d,m] )
// Hft = full FFT of softplus(H). Output float32 = Re(V), out_size = N*M.

#define N_ROWS 1024
#define RANK   16
#define M_LEN  4096
#define LOG2M  12

__device__ float2 g_Hft[RANK * M_LEN];

__device__ __forceinline__ float softplus_accurate(float x) {
    return (x > 20.0f) ? x : log1pf(expf(x));
}

// Packed f32x2 helpers (Blackwell FFMA2 — only reachable via PTX).
__device__ __forceinline__ unsigned long long pack2(float lo, float hi) {
    unsigned long long r;
    asm("mov.b64 %0, {%1, %2};" : "=l"(r) : "f"(lo), "f"(hi));
    return r;
}
__device__ __forceinline__ void unpack2(unsigned long long v, float& lo, float& hi) {
    asm("mov.b64 {%0, %1}, %2;" : "=f"(lo), "=f"(hi) : "l"(v));
}
#define FMA2(dst, a, b, c) \
    asm("fma.rn.f32x2 %0, %1, %2, %3;" : "=l"(dst) : "l"(a), "l"(b), "l"(c))

// ---------------------------------------------------------------------------
// Kernel 1: 16 x 4096-pt FFT of softplus(H) rows (validated; unchanged).
// ---------------------------------------------------------------------------
#define FFT_THREADS 1024

__global__ void __launch_bounds__(FFT_THREADS) fft_hft_kernel(const float* __restrict__ H) {
    __shared__ float2 buf[M_LEN];
    __shared__ float2 tw[M_LEN / 2];
    const int row = blockIdx.x;
    const int tid = threadIdx.x;

    for (int j = tid; j < M_LEN / 2; j += FFT_THREADS) {
        float s, c;
        sincospif(-2.0f * (float)j / (float)M_LEN, &s, &c);
        tw[j] = make_float2(c, s);
    }
    for (int i = tid; i < M_LEN; i += FFT_THREADS) {
        int j = __brev((unsigned)i) >> (32 - LOG2M);
        float v = softplus_accurate(H[row * M_LEN + i]);
        buf[j] = make_float2(v, 0.0f);
    }
    __syncthreads();

    #pragma unroll 1
    for (int s = 1; s <= LOG2M; s++) {
        const int half = 1 << (s - 1);
        const int tsh  = LOG2M - s;
        for (int j = tid; j < (M_LEN / 2); j += FFT_THREADS) {
            int k   = j & (half - 1);
            int grp = j >> (s - 1);
            int i1  = grp * (half << 1) + k;
            int i2  = i1 + half;
            float2 w = tw[k << tsh];
            float2 a = buf[i1];
            float2 b = buf[i2];
            float tr = w.x * b.x - w.y * b.y;
            float ti = w.x * b.y + w.y * b.x;
            buf[i2] = make_float2(a.x - tr, a.y - ti);
            buf[i1] = make_float2(a.x + tr, a.y + ti);
        }
        __syncthreads();
    }

    for (int i = tid; i < M_LEN; i += FFT_THREADS) {
        g_Hft[row * M_LEN + i] = buf[i];
    }
}

// ---------------------------------------------------------------------------
// Kernel 2: packed-f32x2 formulation.
//   v_j = s_j * c_j  with s = (+,+,-,-) repeating:
//     v_{j+1} = (+k) v_j + v_{j-1}  (j even)
//     v_{j+1} = (-k) v_j + v_{j-1}  (j odd)      -> pure fma2, no negations.
//   acc2 += v2 .* h2  per (d, output);  Re = +-(acc.x - acc.y) with sign s_it.
// Warp owns 2 n-rows, lanes span 256 m; 4 d-passes of 4 ranks.
// ---------------------------------------------------------------------------
#define CHUNK_M 256
#define DPASS   4
#define NPASSES (RANK / DPASS)
#define ROWS_W  2
#define WARPS_PER_CTA 8
#define TWO_PI 6.28318530717958647692f

__global__ void __launch_bounds__(256, 2) shiftnmf_main_kernel(
    const float* __restrict__ W,
    const float* __restrict__ tau,
    float* __restrict__ out,
    unsigned long long max_elems)
{
    __shared__ float2 sh[DPASS * CHUNK_M];   // 8 KB

    const int tid    = threadIdx.x;
    const int lane   = tid & 31;
    const int warp   = tid >> 5;
    const int m_base = blockIdx.x * CHUNK_M;
    const int n0     = (blockIdx.y * WARPS_PER_CTA + warp) * ROWS_W;

    unsigned long long acc2[ROWS_W][8];
    #pragma unroll
    for (int r = 0; r < ROWS_W; r++)
        #pragma unroll
        for (int i = 0; i < 8; i++) acc2[r][i] = 0ULL;

    const float inv_m = 1.0f / (float)M_LEN;
    const int m0 = m_base + lane;

    #pragma unroll 1
    for (int pass = 0; pass < NPASSES; pass++) {
        const int dbase = pass * DPASS;

        // Seed packed state: A2 = v_0 = c_0;  B2 = v_{-1} = -c_{-1};
        // KP2 = (k,k); KN2 = (-k,-k);  k = 2*cos(2*pi*tau*32/M).
        unsigned long long A2[ROWS_W][DPASS], B2[ROWS_W][DPASS];
        unsigned long long KP2[ROWS_W][DPASS], KN2[ROWS_W][DPASS];
        #pragma unroll
        for (int r = 0; r < ROWS_W; r++) {
            #pragma unroll
            for (int d = 0; d < DPASS; d++) {
                float t  = __ldg(&tau[(n0 + r) * RANK + dbase + d]);
                float wv = __ldg(&W[(n0 + r) * RANK + dbase + d]);
                float sw = softplus_accurate(wv);
                float s0, c0;
                __sincosf(-TWO_PI * t * ((float)m0 * inv_m), &s0, &c0);
                float cr = sw * c0;
                float ci = sw * s0;
                float ss, cs;
                __sincosf(-TWO_PI * t * (32.0f * inv_m), &ss, &cs);  // om = (cs, ss)
                float k = 2.0f * cs;
                // c_{-1} = c_0 * conj(om); B2 = -c_{-1}
                float bx = -fmaf(cr, cs,  ci * ss);
                float by =  fmaf(cr, ss, -ci * cs);
                A2[r][d]  = pack2(cr, ci);
                B2[r][d]  = pack2(bx, by);
                KP2[r][d] = pack2(k, k);
                KN2[r][d] = pack2(-k, -k);
            }
        }

        __syncthreads();   // prior pass's smem reads complete
        #pragma unroll
        for (int q = 0; q < 2; q++) {
            int idx = q * 256 + tid;
            int d   = idx >> 7;
            int e   = idx & 127;
            float4 v = *reinterpret_cast<const float4*>(
                &g_Hft[(dbase + d) * M_LEN + m_base + e * 2]);
            *reinterpret_cast<float4*>(&sh[d * CHUNK_M + e * 2]) = v;
        }
        __syncthreads();

        #pragma unroll
        for (int it = 0; it < 8; it++) {
            const int ml = it * 32 + lane;
            #pragma unroll
            for (int d = 0; d < DPASS; d++) {
                unsigned long long h2 =
                    *reinterpret_cast<const unsigned long long*>(&sh[d * CHUNK_M + ml]);
                #pragma unroll
                for (int r = 0; r < ROWS_W; r++) {
                    if ((it & 1) == 0) {
                        FMA2(acc2[r][it], A2[r][d], h2, acc2[r][it]);   // use v_it = A2
                        FMA2(B2[r][d], KP2[r][d], A2[r][d], B2[r][d]);  // v_{it+1}
                    } else {
                        FMA2(acc2[r][it], B2[r][d], h2, acc2[r][it]);   // use v_it = B2
                        FMA2(A2[r][d], KN2[r][d], B2[r][d], A2[r][d]);  // v_{it+1}
                    }
                }
            }
        }
    }

    #pragma unroll
    for (int r = 0; r < ROWS_W; r++) {
        const unsigned long long row_base =
            (unsigned long long)(n0 + r) * M_LEN + m_base;
        #pragma unroll
        for (int it = 0; it < 8; it++) {
            float ax, ay;
            unpack2(acc2[r][it], ax, ay);
            // s_it = + for it mod 4 in {0,1}, - for {2,3}
            float val = ((it & 2) == 0) ? (ax - ay) : (ay - ax);
            unsigned long long fi = row_base + (unsigned long long)(it * 32 + lane);
            if (fi < max_elems) out[fi] = val;
        }
    }
}

// ---------------------------------------------------------------------------
extern "C" void kernel_launch(void* const* d_in, const int* in_sizes, int n_in,
                              void* d_out, int out_size) {
    // H = strictly largest input; remaining two in given order = W, tau_tilde.
    int hi = 0;
    for (int i = 1; i < n_in; i++)
        if (in_sizes[i] > in_sizes[hi]) hi = i;

    const float* H = (const float*)d_in[hi];
    const float* wt[2] = {nullptr, nullptr};
    int nwt = 0;
    for (int i = 0; i < n_in && nwt < 2; i++)
        if (i != hi) wt[nwt++] = (const float*)d_in[i];
    const float* W   = wt[0];
    const float* tau = (wt[1] != nullptr) ? wt[1] : wt[0];

    float* out = (float*)d_out;

    unsigned long long max_elems = (unsigned long long)out_size;
    const unsigned long long full = (unsigned long long)N_ROWS * M_LEN;
    if (max_elems > full) max_elems = full;

    fft_hft_kernel<<<RANK, FFT_THREADS>>>(H);

    dim3 grid(M_LEN / CHUNK_M, N_ROWS / (WARPS_PER_CTA * ROWS_W));  // (16, 64)
    shiftnmf_main_kernel<<<grid, 256>>>(W, tau, out, max_elems);
}

// round 9
// speedup vs baseline: 1.5743x; 1.3647x over previous
#include <cuda_runtime.h>
#include <cuda_bf16.h>
#include <math_constants.h>

// ShiftNMF: out[n,m] = Re( sum_d softplus(W[n,d]) * exp(-2*pi*i*tau[n,d]*m/M) * Hft[d,m] )
// Hft = full FFT of softplus(H). Output float32 = Re(V), out_size = N*M.

#define N_ROWS 1024
#define RANK   16
#define M_LEN  4096
#define LOG2M  12

__device__ float2 g_Hft[RANK * M_LEN];

__device__ __forceinline__ float softplus_accurate(float x) {
    return (x > 20.0f) ? x : log1pf(expf(x));
}

// Packed f32x2 helpers (Blackwell FFMA2 — only reachable via PTX).
__device__ __forceinline__ unsigned long long pack2(float lo, float hi) {
    unsigned long long r;
    asm("mov.b64 %0, {%1, %2};" : "=l"(r) : "f"(lo), "f"(hi));
    return r;
}
__device__ __forceinline__ void unpack2(unsigned long long v, float& lo, float& hi) {
    asm("mov.b64 {%0, %1}, %2;" : "=f"(lo), "=f"(hi) : "l"(v));
}
#define FMA2(dst, a, b, c) \
    asm("fma.rn.f32x2 %0, %1, %2, %3;" : "=l"(dst) : "l"(a), "l"(b), "l"(c))

// ---------------------------------------------------------------------------
// Kernel 1: 16 x 4096-pt FFT of softplus(H) rows (validated; unchanged).
// ---------------------------------------------------------------------------
#define FFT_THREADS 1024

__global__ void __launch_bounds__(FFT_THREADS) fft_hft_kernel(const float* __restrict__ H) {
    __shared__ float2 buf[M_LEN];
    __shared__ float2 tw[M_LEN / 2];
    const int row = blockIdx.x;
    const int tid = threadIdx.x;

    for (int j = tid; j < M_LEN / 2; j += FFT_THREADS) {
        float s, c;
        sincospif(-2.0f * (float)j / (float)M_LEN, &s, &c);
        tw[j] = make_float2(c, s);
    }
    for (int i = tid; i < M_LEN; i += FFT_THREADS) {
        int j = __brev((unsigned)i) >> (32 - LOG2M);
        float v = softplus_accurate(H[row * M_LEN + i]);
        buf[j] = make_float2(v, 0.0f);
    }
    __syncthreads();

    #pragma unroll 1
    for (int s = 1; s <= LOG2M; s++) {
        const int half = 1 << (s - 1);
        const int tsh  = LOG2M - s;
        for (int j = tid; j < (M_LEN / 2); j += FFT_THREADS) {
            int k   = j & (half - 1);
            int grp = j >> (s - 1);
            int i1  = grp * (half << 1) + k;
            int i2  = i1 + half;
            float2 w = tw[k << tsh];
            float2 a = buf[i1];
            float2 b = buf[i2];
            float tr = w.x * b.x - w.y * b.y;
            float ti = w.x * b.y + w.y * b.x;
            buf[i2] = make_float2(a.x - tr, a.y - ti);
            buf[i1] = make_float2(a.x + tr, a.y + ti);
        }
        __syncthreads();
    }

    for (int i = tid; i < M_LEN; i += FFT_THREADS) {
        g_Hft[row * M_LEN + i] = buf[i];
    }
}

// ---------------------------------------------------------------------------
// Kernel 2. CTA = 256 thr = 8 warps; each warp owns 2 n-rows; lanes span m.
// CTA tile: 16 n-rows x 512 m. 8 d-passes of 2 ranks.
// Prologue: one thread per (n_local, d) computes (softplus(W), p=-2pi*tau/M,
// cos/sin of 32-step angle) into a 4 KB smem table -> seeds are ~12 instrs.
// Inner: sign-transformed Chebyshev, pure fma.rn.f32x2 (validated R8).
// ---------------------------------------------------------------------------
#define CHUNK_M 512
#define M_ITERS (CHUNK_M / 32)           // 16
#define DPASS   2
#define NPASSES (RANK / DPASS)           // 8
#define ROWS_W  2
#define WARPS_PER_CTA 8
#define ROWS_CTA (WARPS_PER_CTA * ROWS_W) // 16
#define TWO_PI 6.28318530717958647692f

__global__ void __launch_bounds__(256, 2) shiftnmf_main_kernel(
    const float* __restrict__ W,
    const float* __restrict__ tau,
    float* __restrict__ out,
    unsigned long long max_elems)
{
    __shared__ float2 sh[DPASS * CHUNK_M];       // 8 KB
    __shared__ float4 tb[ROWS_CTA * RANK];       // 4 KB: (sw, p, cs, ss)

    const int tid    = threadIdx.x;
    const int lane   = tid & 31;
    const int warp   = tid >> 5;
    const int m_base = blockIdx.x * CHUNK_M;
    const int nblk   = blockIdx.y * ROWS_CTA;

    // Prologue: per-(n_local, d) table, one thread each (256 == blockDim).
    {
        const int rl = tid >> 4;          // n_local 0..15
        const int d  = tid & 15;
        const int n  = nblk + rl;
        float t  = tau[n * RANK + d];
        float wv = W[n * RANK + d];
        float sw = softplus_accurate(wv);
        float ss, cs;
        sincospif(-t * (32.0f * 2.0f / (float)M_LEN), &ss, &cs);  // step angle
        tb[rl * RANK + d] = make_float4(sw, -TWO_PI * t / (float)M_LEN, cs, ss);
    }
    // (table consumed after the first tile-load __syncthreads below)

    unsigned long long acc2[ROWS_W][M_ITERS];
    #pragma unroll
    for (int r = 0; r < ROWS_W; r++)
        #pragma unroll
        for (int i = 0; i < M_ITERS; i++) acc2[r][i] = 0ULL;

    const float fm0 = (float)(m_base + lane);

    #pragma unroll 1
    for (int pass = 0; pass < NPASSES; pass++) {
        const int dbase = pass * DPASS;

        __syncthreads();   // prior pass's reads done; pass0: table ready
        // Load tile: 2 rows x 512 complex = 512 float4; 2 per thread.
        #pragma unroll
        for (int q = 0; q < 2; q++) {
            int idx = q * 256 + tid;
            int d   = idx >> 8;               // 256 float4 per row
            int e   = idx & 255;
            float4 v = *reinterpret_cast<const float4*>(
                &g_Hft[(dbase + d) * M_LEN + m_base + e * 2]);
            *reinterpret_cast<float4*>(&sh[d * CHUNK_M + e * 2]) = v;
        }

        // Seed packed rotators from the smem table (broadcast LDS.128).
        unsigned long long A2[ROWS_W][DPASS], B2[ROWS_W][DPASS];
        unsigned long long KP2[ROWS_W][DPASS], KN2[ROWS_W][DPASS];
        #pragma unroll
        for (int r = 0; r < ROWS_W; r++) {
            #pragma unroll
            for (int d = 0; d < DPASS; d++) {
                float4 e = tb[(warp * ROWS_W + r) * RANK + dbase + d];
                float s0, c0;
                __sincosf(e.y * fm0, &s0, &c0);
                float cr = e.x * c0;
                float ci = e.x * s0;
                float k  = e.z + e.z;
                A2[r][d]  = pack2(cr, ci);
                // B2 = -c_{-1} = -(c0 * conj(om))
                B2[r][d]  = pack2(-fmaf(cr, e.z,  ci * e.w),
                                   fmaf(cr, e.w, -ci * e.z));
                KP2[r][d] = pack2(k, k);
                KN2[r][d] = pack2(-k, -k);
            }
        }
        __syncthreads();   // tile visible

        #pragma unroll
        for (int it = 0; it < M_ITERS; it++) {
            const int ml = it * 32 + lane;
            #pragma unroll
            for (int d = 0; d < DPASS; d++) {
                unsigned long long h2 =
                    *reinterpret_cast<const unsigned long long*>(&sh[d * CHUNK_M + ml]);
                #pragma unroll
                for (int r = 0; r < ROWS_W; r++) {
                    if ((it & 1) == 0) {
                        FMA2(acc2[r][it], A2[r][d], h2, acc2[r][it]);
                        FMA2(B2[r][d], KP2[r][d], A2[r][d], B2[r][d]);
                    } else {
                        FMA2(acc2[r][it], B2[r][d], h2, acc2[r][it]);
                        FMA2(A2[r][d], KN2[r][d], B2[r][d], A2[r][d]);
                    }
                }
            }
        }
    }

    #pragma unroll
    for (int r = 0; r < ROWS_W; r++) {
        const unsigned long long row_base =
            (unsigned long long)(nblk + warp * ROWS_W + r) * M_LEN + m_base;
        #pragma unroll
        for (int it = 0; it < M_ITERS; it++) {
            float ax, ay;
            unpack2(acc2[r][it], ax, ay);
            float val = ((it & 2) == 0) ? (ax - ay) : (ay - ax);
            unsigned long long fi = row_base + (unsigned long long)(it * 32 + lane);
            if (fi < max_elems) out[fi] = val;
        }
    }
}

// ---------------------------------------------------------------------------
extern "C" void kernel_launch(void* const* d_in, const int* in_sizes, int n_in,
                              void* d_out, int out_size) {
    // H = strictly largest input; remaining two in given order = W, tau_tilde.
    int hi = 0;
    for (int i = 1; i < n_in; i++)
        if (in_sizes[i] > in_sizes[hi]) hi = i;

    const float* H = (const float*)d_in[hi];
    const float* wt[2] = {nullptr, nullptr};
    int nwt = 0;
    for (int i = 0; i < n_in && nwt < 2; i++)
        if (i != hi) wt[nwt++] = (const float*)d_in[i];
    const float* W   = wt[0];
    const float* tau = (wt[1] != nullptr) ? wt[1] : wt[0];

    float* out = (float*)d_out;

    unsigned long long max_elems = (unsigned long long)out_size;
    const unsigned long long full = (unsigned long long)N_ROWS * M_LEN;
    if (max_elems > full) max_elems = full;

    fft_hft_kernel<<<RANK, FFT_THREADS>>>(H);

    dim3 grid(M_LEN / CHUNK_M, N_ROWS / ROWS_CTA);  // (8, 64)
    shiftnmf_main_kernel<<<grid, 256>>>(W, tau, out, max_elems);
}

// round 10
// speedup vs baseline: 1.8797x; 1.1940x over previous
#include <cuda_runtime.h>
#include <cuda_bf16.h>
#include <math_constants.h>

// ShiftNMF: out[n,m] = Re( sum_d softplus(W[n,d]) * exp(-2*pi*i*tau[n,d]*m/M) * Hft[d,m] )
// Hft = full FFT of softplus(H). Output float32 = Re(V), out_size = N*M.

#define N_ROWS 1024
#define RANK   16
#define M_LEN  4096
#define LOG2M  12

__device__ float2 g_Hft[RANK * M_LEN];

__device__ __forceinline__ float softplus_accurate(float x) {
    return (x > 20.0f) ? x : log1pf(expf(x));
}
__device__ __forceinline__ float2 cmul(float2 a, float2 b) {
    return make_float2(a.x * b.x - a.y * b.y, a.x * b.y + a.y * b.x);
}

// Packed f32x2 helpers (Blackwell FFMA2 — only reachable via PTX).
__device__ __forceinline__ unsigned long long pack2(float lo, float hi) {
    unsigned long long r;
    asm("mov.b64 %0, {%1, %2};" : "=l"(r) : "f"(lo), "f"(hi));
    return r;
}
__device__ __forceinline__ void unpack2(unsigned long long v, float& lo, float& hi) {
    asm("mov.b64 {%0, %1}, %2;" : "=f"(lo), "=f"(hi) : "l"(v));
}
#define FMA2(dst, a, b, c) \
    asm("fma.rn.f32x2 %0, %1, %2, %3;" : "=l"(dst) : "l"(a), "l"(b), "l"(c))

// ---------------------------------------------------------------------------
// Kernel 1: 16 x 4096-pt FFT of softplus(H), radix-4 DIT (6 stages).
// One CTA per row, 1024 threads = 1 butterfly/thread/stage.
// ---------------------------------------------------------------------------
#define FFT_THREADS 1024

__global__ void __launch_bounds__(FFT_THREADS) fft_hft_kernel(const float* __restrict__ H) {
    __shared__ float2 buf[M_LEN];        // 32 KB
    __shared__ float2 tw[M_LEN / 2];     // 16 KB: exp(-2*pi*i*j/4096), j<2048
    const int row = blockIdx.x;
    const int tid = threadIdx.x;

    for (int j = tid; j < M_LEN / 2; j += FFT_THREADS) {
        float s, c;
        sincospif(-2.0f * (float)j / (float)M_LEN, &s, &c);
        tw[j] = make_float2(c, s);
    }
    // Base-4 digit-reversed load: bitrev(12b) then swap adjacent bit pairs.
    for (int i = tid; i < M_LEN; i += FFT_THREADS) {
        unsigned r = __brev((unsigned)i) >> (32 - LOG2M);
        r = ((r & 0x555u) << 1) | ((r >> 1) & 0x555u);
        float v = softplus_accurate(H[row * M_LEN + i]);
        buf[r] = make_float2(v, 0.0f);
    }
    __syncthreads();

    // 6 radix-4 stages. Stage s: sub-FFT len = 4^s, quarter q = 4^(s-1).
    #pragma unroll 1
    for (int s = 1; s <= 6; s++) {
        const int q   = 1 << (2 * (s - 1));
        const int tsh = LOG2M - 2 * s;           // k -> twiddle idx shift
        const int k   = tid & (q - 1);
        const int g   = tid >> (2 * (s - 1));
        const int base = g * (q << 2) + k;

        float2 y0 = buf[base];
        float2 y1 = buf[base + q];
        float2 y2 = buf[base + 2 * q];
        float2 y3 = buf[base + 3 * q];

        float2 w1 = tw[k << tsh];
        float2 w2 = tw[(2 * k) << tsh];
        float2 w3 = cmul(w1, w2);

        float2 t1 = cmul(w1, y1);
        float2 t2 = cmul(w2, y2);
        float2 t3 = cmul(w3, y3);

        float2 u0 = make_float2(y0.x + t2.x, y0.y + t2.y);
        float2 u1 = make_float2(y0.x - t2.x, y0.y - t2.y);
        float2 u2 = make_float2(t1.x + t3.x, t1.y + t3.y);
        float2 u3 = make_float2(t1.x - t3.x, t1.y - t3.y);

        buf[base]         = make_float2(u0.x + u2.x, u0.y + u2.y);
        buf[base + 2 * q] = make_float2(u0.x - u2.x, u0.y - u2.y);
        // -j*u3 = (u3.y, -u3.x); +j*u3 = (-u3.y, u3.x)
        buf[base + q]     = make_float2(u1.x + u3.y, u1.y - u3.x);
        buf[base + 3 * q] = make_float2(u1.x - u3.y, u1.y + u3.x);
        __syncthreads();
    }

    for (int i = tid; i < M_LEN; i += FFT_THREADS) {
        g_Hft[row * M_LEN + i] = buf[i];
    }
}

// ---------------------------------------------------------------------------
// Kernel 2. CTA = 256 thr = 8 warps; warp owns 2 n-rows; lanes span m.
// CTA tile: 16 n-rows x 512 m. 8 d-passes of 2 ranks, DOUBLE-BUFFERED:
// next pass's Hft tile is prefetched (LDG) before compute, stored (STS)
// after compute -> 1 barrier/pass, GMEM latency hidden behind FFMA2 work.
// Seed table (softplus/step-trig per (n_local,d)) computed once in prologue.
// ---------------------------------------------------------------------------
#define CHUNK_M 512
#define M_ITERS (CHUNK_M / 32)            // 16
#define DPASS   2
#define NPASSES (RANK / DPASS)            // 8
#define ROWS_W  2
#define WARPS_PER_CTA 8
#define ROWS_CTA (WARPS_PER_CTA * ROWS_W) // 16
#define TWO_PI 6.28318530717958647692f

__global__ void __launch_bounds__(256, 2) shiftnmf_main_kernel(
    const float* __restrict__ W,
    const float* __restrict__ tau,
    float* __restrict__ out,
    unsigned long long max_elems)
{
    __shared__ float2 sh[2][DPASS * CHUNK_M];    // 16 KB ping-pong
    __shared__ float4 tb[ROWS_CTA * RANK];       // 4 KB: (sw, p, cs, ss)

    const int tid    = threadIdx.x;
    const int lane   = tid & 31;
    const int warp   = tid >> 5;
    const int m_base = blockIdx.x * CHUNK_M;
    const int nblk   = blockIdx.y * ROWS_CTA;

    // Prologue seed table: one thread per (n_local, d).
    {
        const int rl = tid >> 4;
        const int d  = tid & 15;
        const int n  = nblk + rl;
        float t  = tau[n * RANK + d];
        float sw = softplus_accurate(W[n * RANK + d]);
        float ss, cs;
        sincospif(-t * (64.0f / (float)M_LEN), &ss, &cs);   // 32-step angle
        tb[rl * RANK + d] = make_float4(sw, -TWO_PI * t / (float)M_LEN, cs, ss);
    }

    // Tile-load addressing (2 float4 per thread per pass).
    const int ld_d0 = (tid >> 8);            // always 0 for q=0
    const int ld_e0 = tid & 255;
    const int ld_d1 = ((256 + tid) >> 8);    // always 1
    const int ld_e1 = tid & 255;

    // Load pass 0 tile into buffer 0.
    {
        float4 v0 = *reinterpret_cast<const float4*>(
            &g_Hft[ld_d0 * M_LEN + m_base + ld_e0 * 2]);
        float4 v1 = *reinterpret_cast<const float4*>(
            &g_Hft[ld_d1 * M_LEN + m_base + ld_e1 * 2]);
        *reinterpret_cast<float4*>(&sh[0][ld_d0 * CHUNK_M + ld_e0 * 2]) = v0;
        *reinterpret_cast<float4*>(&sh[0][ld_d1 * CHUNK_M + ld_e1 * 2]) = v1;
    }
    __syncthreads();   // tile 0 + seed table visible

    unsigned long long acc2[ROWS_W][M_ITERS];
    #pragma unroll
    for (int r = 0; r < ROWS_W; r++)
        #pragma unroll
        for (int i = 0; i < M_ITERS; i++) acc2[r][i] = 0ULL;

    const float fm0 = (float)(m_base + lane);

    #pragma unroll 1
    for (int pass = 0; pass < NPASSES; pass++) {
        const int dbase = pass * DPASS;
        const float2* __restrict__ cur = sh[pass & 1];

        // Prefetch next pass's tile into registers (hides L2 latency).
        float4 p0, p1;
        if (pass < NPASSES - 1) {
            const int nb = (pass + 1) * DPASS;
            p0 = *reinterpret_cast<const float4*>(
                &g_Hft[(nb + ld_d0) * M_LEN + m_base + ld_e0 * 2]);
            p1 = *reinterpret_cast<const float4*>(
                &g_Hft[(nb + ld_d1) * M_LEN + m_base + ld_e1 * 2]);
        }

        // Seed packed rotators from the smem table.
        unsigned long long A2[ROWS_W][DPASS], B2[ROWS_W][DPASS];
        unsigned long long KP2[ROWS_W][DPASS], KN2[ROWS_W][DPASS];
        #pragma unroll
        for (int r = 0; r < ROWS_W; r++) {
            #pragma unroll
            for (int d = 0; d < DPASS; d++) {
                float4 e = tb[(warp * ROWS_W + r) * RANK + dbase + d];
                float s0, c0;
                __sincosf(e.y * fm0, &s0, &c0);
                float cr = e.x * c0;
                float ci = e.x * s0;
                float k  = e.z + e.z;
                A2[r][d]  = pack2(cr, ci);
                B2[r][d]  = pack2(-fmaf(cr, e.z,  ci * e.w),
                                   fmaf(cr, e.w, -ci * e.z));
                KP2[r][d] = pack2(k, k);
                KN2[r][d] = pack2(-k, -k);
            }
        }

        #pragma unroll
        for (int it = 0; it < M_ITERS; it++) {
            const int ml = it * 32 + lane;
            #pragma unroll
            for (int d = 0; d < DPASS; d++) {
                unsigned long long h2 =
                    *reinterpret_cast<const unsigned long long*>(&cur[d * CHUNK_M + ml]);
                #pragma unroll
                for (int r = 0; r < ROWS_W; r++) {
                    if ((it & 1) == 0) {
                        FMA2(acc2[r][it], A2[r][d], h2, acc2[r][it]);
                        FMA2(B2[r][d], KP2[r][d], A2[r][d], B2[r][d]);
                    } else {
                        FMA2(acc2[r][it], B2[r][d], h2, acc2[r][it]);
                        FMA2(A2[r][d], KN2[r][d], B2[r][d], A2[r][d]);
                    }
                }
            }
        }

        // Stage next tile into the other buffer; single barrier per pass.
        if (pass < NPASSES - 1) {
            float2* nxt = sh[(pass + 1) & 1];
            *reinterpret_cast<float4*>(&nxt[ld_d0 * CHUNK_M + ld_e0 * 2]) = p0;
            *reinterpret_cast<float4*>(&nxt[ld_d1 * CHUNK_M + ld_e1 * 2]) = p1;
            __syncthreads();
        }
    }

    #pragma unroll
    for (int r = 0; r < ROWS_W; r++) {
        const unsigned long long row_base =
            (unsigned long long)(nblk + warp * ROWS_W + r) * M_LEN + m_base;
        #pragma unroll
        for (int it = 0; it < M_ITERS; it++) {
            float ax, ay;
            unpack2(acc2[r][it], ax, ay);
            float val = ((it & 2) == 0) ? (ax - ay) : (ay - ax);
            unsigned long long fi = row_base + (unsigned long long)(it * 32 + lane);
            if (fi < max_elems) out[fi] = val;
        }
    }
}

// ---------------------------------------------------------------------------
extern "C" void kernel_launch(void* const* d_in, const int* in_sizes, int n_in,
                              void* d_out, int out_size) {
    // H = strictly largest input; remaining two in given order = W, tau_tilde.
    int hi = 0;
    for (int i = 1; i < n_in; i++)
        if (in_sizes[i] > in_sizes[hi]) hi = i;

    const float* H = (const float*)d_in[hi];
    const float* wt[2] = {nullptr, nullptr};
    int nwt = 0;
    for (int i = 0; i < n_in && nwt < 2; i++)
        if (i != hi) wt[nwt++] = (const float*)d_in[i];
    const float* W   = wt[0];
    const float* tau = (wt[1] != nullptr) ? wt[1] : wt[0];

    float* out = (float*)d_out;

    unsigned long long max_elems = (unsigned long long)out_size;
    const unsigned long long full = (unsigned long long)N_ROWS * M_LEN;
    if (max_elems > full) max_elems = full;

    fft_hft_kernel<<<RANK, FFT_THREADS>>>(H);

    dim3 grid(M_LEN / CHUNK_M, N_ROWS / ROWS_CTA);  // (8, 64)
    shiftnmf_main_kernel<<<grid, 256>>>(W, tau, out, max_elems);
}